// round 15
// baseline (speedup 1.0000x reference)
#include <cuda_runtime.h>
#include <cuda_bf16.h>
#include <cuda_fp16.h>
#include <mma.h>
#include <cstdint>
#include <cstddef>

using namespace nvcuda;

// Problem shape (fixed): B=2, S=2048, D=1024, H=16, Dh=64
#define NB 2
#define NS 2048
#define ND 1024
#define NH 16
#define NDH 64
#define TOK (NB*NS)
#define OUT_ELEMS (4194304)
#define SCALE 0.125f
#define LN_EPS 1e-5f

// ---- scratch (__device__ globals; no allocation allowed) ----
__device__ float g_fc[TOK*ND];                 // fc projection output (f32)
__device__ float g_inv[32 * NS];               // 1/rowsum per [bh][row]
__device__ __half g_Qh[TOK*ND];                // fp16 Q projection
__device__ __half g_Kh[TOK*ND];                // fp16 K projection
__device__ __half g_inQh[TOK*ND];              // fp16 input_Q
__device__ __half g_WQh[ND*ND];                // fp16 W_Q
__device__ __half g_inKh[TOK*ND];              // fp16 input_K
__device__ __half g_WKh[ND*ND];                // fp16 W_K
__device__ __nv_bfloat16 g_inVh[TOK*ND];       // bf16 input_V
__device__ __nv_bfloat16 g_WVh[ND*ND];         // bf16 W_V
__device__ __nv_bfloat16 g_Wfch[ND*ND];        // bf16 W_fc
__device__ __nv_bfloat16 g_Vh[TOK*ND];         // bf16 V projection
__device__ __nv_bfloat16 g_ctxh[TOK*ND];       // bf16 context

// ---------------------------------------------------------------------------
__device__ __forceinline__ void cpa16(void* s, const void* g) {
    uint32_t sa = (uint32_t)__cvta_generic_to_shared(s);
    asm volatile("cp.async.ca.shared.global [%0], [%1], 16;" :: "r"(sa), "l"(g));
}
__device__ __forceinline__ void cpa_commit() {
    asm volatile("cp.async.commit_group;" ::: "memory");
}
template <int N>
__device__ __forceinline__ void cpa_wait() {
    asm volatile("cp.async.wait_group %0;" :: "n"(N) : "memory");
}

__device__ __forceinline__ uint32_t pack_bf2(float a, float b) {
    __nv_bfloat162 t = __float22bfloat162_rn(make_float2(a, b));
    return *(uint32_t*)&t;
}
__device__ __forceinline__ uint32_t pack_hf2(float a, float b) {
    __half2 t = __float22half2_rn(make_float2(a, b));
    return *(uint32_t*)&t;
}

// ---------------------------------------------------------------------------
// One launch converting all 7 inputs: z=0..3 -> fp16 (QK path),
// z=4..6 -> bf16 (V/fc path).
// ---------------------------------------------------------------------------
__global__ __launch_bounds__(256) void cvt_all(const float* __restrict__ inQ,
                                               const float* __restrict__ WQ,
                                               const float* __restrict__ inK,
                                               const float* __restrict__ WK,
                                               const float* __restrict__ inV,
                                               const float* __restrict__ WV,
                                               const float* __restrict__ Wfc) {
    const int z = blockIdx.y;
    const int n = (z == 0 || z == 2 || z == 4) ? TOK * ND : ND * ND;
    int i = (blockIdx.x * 256 + threadIdx.x) * 4;
    if (i >= n) return;
    const float* s;
    switch (z) {
        case 0: s = inQ; break;
        case 1: s = WQ; break;
        case 2: s = inK; break;
        case 3: s = WK; break;
        case 4: s = inV; break;
        case 5: s = WV; break;
        default: s = Wfc; break;
    }
    float4 v = *(const float4*)&s[i];
    if (z < 4) {
        __half* d = (z == 0) ? g_inQh : (z == 1) ? g_WQh : (z == 2) ? g_inKh : g_WKh;
        *(uint32_t*)&d[i]     = pack_hf2(v.x, v.y);
        *(uint32_t*)&d[i + 2] = pack_hf2(v.z, v.w);
    } else {
        __nv_bfloat16* d = (z == 4) ? g_inVh : (z == 5) ? g_WVh : g_Wfch;
        *(uint32_t*)&d[i]     = pack_bf2(v.x, v.y);
        *(uint32_t*)&d[i + 2] = pack_bf2(v.z, v.w);
    }
}

// ---------------------------------------------------------------------------
// fp16 GEMM with direct fp16 output: C half = A half @ B half (f32 accum).
// BK=32, 2-stage cp.async, BM=BN=128, 8 warps, warp tile 64x32.
// ---------------------------------------------------------------------------
#define LOADHH(sA, sB, A, Bw, st, k0)                                                  \
    {                                                                                  \
        _Pragma("unroll")                                                              \
        for (int i = 0; i < 2; i++) {                                                  \
            int idx = tid + i * 256;                                                   \
            int ra = idx >> 2, ca = (idx & 3) << 3;                                    \
            cpa16(&sA[st][ra][ca], &A[(size_t)(m0 + ra) * ND + (k0) + ca]);            \
            int rb = idx >> 4, cb = (idx & 15) << 3;                                   \
            cpa16(&sB[st][rb][cb], &Bw[(size_t)((k0) + rb) * ND + n0 + cb]);           \
        }                                                                              \
        cpa_commit();                                                                  \
    }

__global__ __launch_bounds__(256, 2) void qk_gemm_h(float dummy) {
    __shared__ __half sA[2][128][40];
    __shared__ __half sB[2][32][136];

    const int tid = threadIdx.x;
    const int w   = tid >> 5;
    const int l   = tid & 31;
    const int wm  = w >> 2;
    const int wn  = w & 3;
    const int m0  = blockIdx.y * 128;
    const int n0  = blockIdx.x * 128;
    const int z   = blockIdx.z;

    const __half* A  = (z == 0) ? g_inQh : g_inKh;
    const __half* Bw = (z == 0) ? g_WQh  : g_WKh;
    __half*       C  = (z == 0) ? g_Qh   : g_Kh;

    wmma::fragment<wmma::accumulator, 16, 16, 16, float> acc[4][2];
#pragma unroll
    for (int i = 0; i < 4; i++)
#pragma unroll
        for (int j = 0; j < 2; j++) wmma::fill_fragment(acc[i][j], 0.0f);

    LOADHH(sA, sB, A, Bw, 0, 0);

    for (int kt = 0; kt < 32; kt++) {
        if (kt < 31) {
            LOADHH(sA, sB, A, Bw, (kt + 1) & 1, (kt + 1) * 32);
            cpa_wait<1>();
        } else {
            cpa_wait<0>();
        }
        __syncthreads();
        const int st = kt & 1;
#pragma unroll
        for (int ks = 0; ks < 32; ks += 16) {
            wmma::fragment<wmma::matrix_a, 16, 16, 16, __half, wmma::row_major> af[4];
            wmma::fragment<wmma::matrix_b, 16, 16, 16, __half, wmma::row_major> bf[2];
#pragma unroll
            for (int i = 0; i < 4; i++)
                wmma::load_matrix_sync(af[i], &sA[st][wm * 64 + i * 16][ks], 40);
#pragma unroll
            for (int j = 0; j < 2; j++)
                wmma::load_matrix_sync(bf[j], &sB[st][ks][wn * 32 + j * 16], 136);
#pragma unroll
            for (int i = 0; i < 4; i++)
#pragma unroll
                for (int j = 0; j < 2; j++)
                    wmma::mma_sync(acc[i][j], af[i], bf[j], acc[i][j]);
        }
        __syncthreads();
    }

    float* stg = (float*)sA + (size_t)w * (16 * 36);
#pragma unroll
    for (int i = 0; i < 4; i++) {
        wmma::store_matrix_sync(&stg[0],  acc[i][0], 36, wmma::mem_row_major);
        wmma::store_matrix_sync(&stg[16], acc[i][1], 36, wmma::mem_row_major);
        __syncwarp();
        const int r  = l & 15;
        const int hf = l >> 4;
        const float* row = stg + r * 36 + hf * 16;
        uint32_t pk[8];
#pragma unroll
        for (int q = 0; q < 8; q++) pk[q] = pack_hf2(row[2 * q], row[2 * q + 1]);
        __half* gp = C + (size_t)(m0 + wm * 64 + i * 16 + r) * ND + n0 + wn * 32 + hf * 16;
        *(uint4*)gp       = make_uint4(pk[0], pk[1], pk[2], pk[3]);
        *(uint4*)(gp + 8) = make_uint4(pk[4], pk[5], pk[6], pk[7]);
        __syncwarp();
    }
}

// ---------------------------------------------------------------------------
// bf16 GEMM: C f32 = A bf16 @ B bf16 (fc projection).
// ---------------------------------------------------------------------------
__global__ __launch_bounds__(256, 2) void gemm_bf16(const __nv_bfloat16* __restrict__ A,
                                                    const __nv_bfloat16* __restrict__ Bw,
                                                    float* __restrict__ C) {
    __shared__ __nv_bfloat16 sA[2][128][40];
    __shared__ __nv_bfloat16 sB[2][32][136];

    const int tid = threadIdx.x;
    const int w   = tid >> 5;
    const int wm  = w >> 2;
    const int wn  = w & 3;
    const int m0  = blockIdx.y * 128;
    const int n0  = blockIdx.x * 128;

    wmma::fragment<wmma::accumulator, 16, 16, 16, float> acc[4][2];
#pragma unroll
    for (int i = 0; i < 4; i++)
#pragma unroll
        for (int j = 0; j < 2; j++) wmma::fill_fragment(acc[i][j], 0.0f);

    LOADHH(sA, sB, A, Bw, 0, 0);

    for (int kt = 0; kt < 32; kt++) {
        if (kt < 31) {
            LOADHH(sA, sB, A, Bw, (kt + 1) & 1, (kt + 1) * 32);
            cpa_wait<1>();
        } else {
            cpa_wait<0>();
        }
        __syncthreads();
        const int st = kt & 1;
#pragma unroll
        for (int ks = 0; ks < 32; ks += 16) {
            wmma::fragment<wmma::matrix_a, 16, 16, 16, __nv_bfloat16, wmma::row_major> af[4];
            wmma::fragment<wmma::matrix_b, 16, 16, 16, __nv_bfloat16, wmma::row_major> bf[2];
#pragma unroll
            for (int i = 0; i < 4; i++)
                wmma::load_matrix_sync(af[i], &sA[st][wm * 64 + i * 16][ks], 40);
#pragma unroll
            for (int j = 0; j < 2; j++)
                wmma::load_matrix_sync(bf[j], &sB[st][ks][wn * 32 + j * 16], 136);
#pragma unroll
            for (int i = 0; i < 4; i++)
#pragma unroll
                for (int j = 0; j < 2; j++)
                    wmma::mma_sync(acc[i][j], af[i], bf[j], acc[i][j]);
        }
        __syncthreads();
    }

#pragma unroll
    for (int i = 0; i < 4; i++)
#pragma unroll
        for (int j = 0; j < 2; j++)
            wmma::store_matrix_sync(&C[(size_t)(m0 + wm * 64 + i * 16) * ND + n0 + wn * 32 + j * 16],
                                    acc[i][j], ND, wmma::mem_row_major);
}

// ---------------------------------------------------------------------------
// bf16 GEMM with DIRECT bf16 output (V projection).
// ---------------------------------------------------------------------------
__global__ __launch_bounds__(256, 2) void gemm_bf16_obf(const __nv_bfloat16* __restrict__ A,
                                                        const __nv_bfloat16* __restrict__ Bw,
                                                        __nv_bfloat16* __restrict__ C) {
    __shared__ __nv_bfloat16 sA[2][128][40];
    __shared__ __nv_bfloat16 sB[2][32][136];

    const int tid = threadIdx.x;
    const int w   = tid >> 5;
    const int l   = tid & 31;
    const int wm  = w >> 2;
    const int wn  = w & 3;
    const int m0  = blockIdx.y * 128;
    const int n0  = blockIdx.x * 128;

    wmma::fragment<wmma::accumulator, 16, 16, 16, float> acc[4][2];
#pragma unroll
    for (int i = 0; i < 4; i++)
#pragma unroll
        for (int j = 0; j < 2; j++) wmma::fill_fragment(acc[i][j], 0.0f);

    LOADHH(sA, sB, A, Bw, 0, 0);

    for (int kt = 0; kt < 32; kt++) {
        if (kt < 31) {
            LOADHH(sA, sB, A, Bw, (kt + 1) & 1, (kt + 1) * 32);
            cpa_wait<1>();
        } else {
            cpa_wait<0>();
        }
        __syncthreads();
        const int st = kt & 1;
#pragma unroll
        for (int ks = 0; ks < 32; ks += 16) {
            wmma::fragment<wmma::matrix_a, 16, 16, 16, __nv_bfloat16, wmma::row_major> af[4];
            wmma::fragment<wmma::matrix_b, 16, 16, 16, __nv_bfloat16, wmma::row_major> bf[2];
#pragma unroll
            for (int i = 0; i < 4; i++)
                wmma::load_matrix_sync(af[i], &sA[st][wm * 64 + i * 16][ks], 40);
#pragma unroll
            for (int j = 0; j < 2; j++)
                wmma::load_matrix_sync(bf[j], &sB[st][ks][wn * 32 + j * 16], 136);
#pragma unroll
            for (int i = 0; i < 4; i++)
#pragma unroll
                for (int j = 0; j < 2; j++)
                    wmma::mma_sync(acc[i][j], af[i], bf[j], acc[i][j]);
        }
        __syncthreads();
    }

    float* stg = (float*)sA + (size_t)w * (16 * 36);
#pragma unroll
    for (int i = 0; i < 4; i++) {
        wmma::store_matrix_sync(&stg[0],  acc[i][0], 36, wmma::mem_row_major);
        wmma::store_matrix_sync(&stg[16], acc[i][1], 36, wmma::mem_row_major);
        __syncwarp();
        const int r  = l & 15;
        const int hf = l >> 4;
        const float* row = stg + r * 36 + hf * 16;
        uint32_t pk[8];
#pragma unroll
        for (int q = 0; q < 8; q++) pk[q] = pack_bf2(row[2 * q], row[2 * q + 1]);
        __nv_bfloat16* gp = C + (size_t)(m0 + wm * 64 + i * 16 + r) * ND + n0 + wn * 32 + hf * 16;
        *(uint4*)gp       = make_uint4(pk[0], pk[1], pk[2], pk[3]);
        *(uint4*)(gp + 8) = make_uint4(pk[4], pk[5], pk[6], pk[7]);
        __syncwarp();
    }
}
#undef LOADHH

// ---------------------------------------------------------------------------
// escore v7.1 — fp16 Q/K, mask in smem, now 3 BLOCKS/SM (regs capped at 85;
// ~9 spills absorbed by L1, 24 resident warps hide exp/store/L1 phases).
// grid = (32, 32), 256 threads.
// ---------------------------------------------------------------------------
#define ESC_SMEM (17408 + 256 + 9216 + 18432 + 12288)   // 57600 B

__global__ __launch_bounds__(256, 3) void escore_kernel(const unsigned char* __restrict__ mask,
                                                        float* __restrict__ attnOut) {
    extern __shared__ float sm[];
    float* sS   = sm;                                   // 64 x 68 f32
    float* sSum = sS + 64 * 68;                         // 64
    __half* sQ  = (__half*)(sSum + 64);                 // 64 x 72 half
    __half* sK  = sQ + 64 * 72;                         // 2 x (64 x 72) half
    unsigned char* sMask = (unsigned char*)(sK + 2 * 64 * 72);  // 3 x 4096

    const int tid = threadIdx.x;
    const int w   = tid >> 5;
    const int l   = tid & 31;
    const int bh  = blockIdx.y;
    const int b   = bh >> 4;
    const int h   = bh & 15;
    const int q0  = blockIdx.x * 64;

    const __half* Qb = g_Qh + ((size_t)(b * NS + q0)) * ND + h * NDH;
    const __half* Kb = g_Kh + ((size_t)b * NS) * ND + h * NDH;
    const unsigned char* Mb = mask + ((size_t)(b * NS + q0)) * NS;

    const int mrw = tid >> 2;
    const int mcc = (tid & 3) << 4;

#pragma unroll
    for (int i = 0; i < 2; i++) {
        int idx = tid + i * 256;
        int r = idx >> 3, c = (idx & 7) << 3;
        cpa16(&sQ[r * 72 + c], &Qb[(size_t)r * ND + c]);
        cpa16(&sK[r * 72 + c], &Kb[(size_t)r * ND + c]);
    }
    cpa16(&sMask[mrw * 64 + mcc], &Mb[(size_t)mrw * NS + mcc]);
    cpa_commit();
    if (tid < 64) sSum[tid] = 0.0f;

    const int wm = w >> 2;
    const int wn = w & 3;

    wmma::fragment<wmma::matrix_a, 16, 16, 16, __half, wmma::row_major> af[2][4];

    int mbuf = 0;

    for (int ct = 0; ct < 32; ct++) {
        const int mnext = (mbuf + 1 == 3) ? 0 : mbuf + 1;
        if (ct < 31) {
            __half* dst = sK + ((ct + 1) & 1) * (64 * 72);
            const __half* src = Kb + (size_t)(ct + 1) * 64 * ND;
#pragma unroll
            for (int i = 0; i < 2; i++) {
                int idx = tid + i * 256;
                int r = idx >> 3, c = (idx & 7) << 3;
                cpa16(&dst[r * 72 + c], &src[(size_t)r * ND + c]);
            }
            cpa16(&sMask[mnext * 4096 + mrw * 64 + mcc],
                  &Mb[(size_t)mrw * NS + (size_t)(ct + 1) * 64 + mcc]);
            cpa_commit();
            cpa_wait<1>();
        } else {
            cpa_wait<0>();
        }
        __syncthreads();   // A: K[ct], M[ct] (and Q at ct=0) visible

        if (ct == 0) {
#pragma unroll
            for (int i = 0; i < 2; i++)
#pragma unroll
                for (int kk = 0; kk < 4; kk++)
                    wmma::load_matrix_sync(af[i][kk], &sQ[(wm * 32 + i * 16) * 72 + kk * 16], 72);
        }

        const __half* sKt = sK + (ct & 1) * (64 * 72);
        wmma::fragment<wmma::accumulator, 16, 16, 16, float> acc[2];
        wmma::fill_fragment(acc[0], 0.0f);
        wmma::fill_fragment(acc[1], 0.0f);

#pragma unroll
        for (int kk = 0; kk < 4; kk++) {
            wmma::fragment<wmma::matrix_b, 16, 16, 16, __half, wmma::col_major> bf;
            wmma::load_matrix_sync(bf, &sKt[(wn * 16) * 72 + kk * 16], 72);
            wmma::mma_sync(acc[0], af[0][kk], bf, acc[0]);
            wmma::mma_sync(acc[1], af[1][kk], bf, acc[1]);
        }
#pragma unroll
        for (int i = 0; i < 2; i++)
            wmma::store_matrix_sync(&sS[(wm * 32 + i * 16) * 68 + wn * 16], acc[i], 68,
                                    wmma::mem_row_major);
        __syncthreads();   // B: sS complete; K buffer reuse guarded

        const int c0 = ct * 64;
        const unsigned char* mTile = sMask + mbuf * 4096;
#pragma unroll
        for (int pass = 0; pass < 4; pass++) {
            const int r  = w * 8 + pass * 2 + (l >> 4);
            const int cc = (l & 15) << 2;
            float4 v = *(const float4*)&sS[r * 68 + cc];
            uchar4 mk = *(const uchar4*)&mTile[r * 64 + cc];
            v.x = mk.x ? 0.0f : __expf(v.x * SCALE);
            v.y = mk.y ? 0.0f : __expf(v.y * SCALE);
            v.z = mk.z ? 0.0f : __expf(v.z * SCALE);
            v.w = mk.w ? 0.0f : __expf(v.w * SCALE);
            float* erow = attnOut + ((size_t)(bh * NS + q0 + r)) * NS + c0;
            *(float4*)&erow[cc] = v;
            float s = v.x + v.y + v.z + v.w;
#pragma unroll
            for (int off = 8; off > 0; off >>= 1)
                s += __shfl_xor_sync(0xffffffffu, s, off);
            if ((l & 15) == 0) sSum[r] += s;
        }
        mbuf = mnext;
    }

    __syncthreads();
    if (tid < 64) g_inv[(size_t)bh * NS + q0 + tid] = 1.0f / sSum[tid];
}

// ---------------------------------------------------------------------------
// ctxnorm v4 — 64-row m-tiles, 256 threads (4 epi + 4 MMA warps), 72KB smem
// -> 3 blocks/SM. Same lagged-V warp-specialized skeleton as v3.1 (race-free:
// group kc = {E[kc+1], V[kc]}; MMA(kc) reads V[kc-1]/P[kc-1], opposite parity
// of concurrent writes; reuse guarded by barrier A).
// grid = (32, 32), 256 threads.
// ---------------------------------------------------------------------------
#define CTX_ER   (2 * 64 * 68 * 4)      // 34816
#define CTX_VH   (2 * 64 * 72 * 2)      // 18432
#define CTX_PB   (2 * 64 * 72 * 2)      // 18432
#define CTX_SMEM (CTX_ER + CTX_VH + CTX_PB + 256)   // 71936

__global__ __launch_bounds__(256, 3) void ctxnorm_kernel(float* __restrict__ attn) {
    extern __shared__ char smc[];
    float*         sEraw = (float*)smc;                               // 2 x 64 x 68
    __nv_bfloat16* sVh   = (__nv_bfloat16*)(smc + CTX_ER);            // 2 x 64 x 72
    __nv_bfloat16* sPb   = (__nv_bfloat16*)(smc + CTX_ER + CTX_VH);   // 2 x 64 x 72
    float*         sInv  = (float*)(smc + CTX_ER + CTX_VH + CTX_PB);  // 64

    const int tid = threadIdx.x;
    const int w   = tid >> 5;
    const int l   = tid & 31;
    const int bh  = blockIdx.y;
    const int b   = bh >> 4;
    const int h   = bh & 15;
    const int m0  = blockIdx.x * 64;

    float* Eb = attn + ((size_t)bh * NS + m0) * NS;
    const __nv_bfloat16* Vb = g_Vh + ((size_t)b * NS) * ND + h * NDH;

    if (tid < 64) sInv[tid] = g_inv[(size_t)bh * NS + m0 + tid];

    // pre-loop group: E chunk 0 only (V[0] comes with iteration 0's group)
#pragma unroll
    for (int i = 0; i < 4; i++) {
        int idx = tid + i * 256;
        int er = idx >> 4, ec = (idx & 15) << 2;
        cpa16(&sEraw[er * 68 + ec], &Eb[(size_t)er * NS + ec]);
    }
    cpa_commit();

    const int wv = w - 4;
    const int wm = wv >> 1, wn = wv & 1;    // MMA warps: 2(m) x 2(n), 32x32
    const int band = w * 16;                // epi warps (w<4): 16-row band

    wmma::fragment<wmma::accumulator, 16, 16, 16, float> acc[2][2];
    if (w >= 4) {
#pragma unroll
        for (int i = 0; i < 2; i++)
#pragma unroll
            for (int j = 0; j < 2; j++) wmma::fill_fragment(acc[i][j], 0.0f);
    }

    for (int kc = 0; kc <= 32; kc++) {
        __syncthreads();   // A: prior compute done -> buffer reuse safe
        if (kc < 32) {
            // group kc: E[kc+1] (if it exists) + V[kc]
            if (kc + 1 < 32) {
                float* dE = sEraw + ((kc + 1) & 1) * (64 * 68);
#pragma unroll
                for (int i = 0; i < 4; i++) {
                    int idx = tid + i * 256;
                    int er = idx >> 4, ec = (idx & 15) << 2;
                    cpa16(&dE[er * 68 + ec],
                          &Eb[(size_t)er * NS + (size_t)(kc + 1) * 64 + ec]);
                }
            }
            {
                __nv_bfloat16* dV = sVh + (kc & 1) * (64 * 72);
#pragma unroll
                for (int i = 0; i < 2; i++) {
                    int idx = tid + i * 256;
                    int vr = idx >> 3, vc = (idx & 7) << 3;
                    cpa16(&dV[vr * 72 + vc], &Vb[(size_t)(kc * 64 + vr) * ND + vc]);
                }
            }
            cpa_commit();
            cpa_wait<1>();   // group kc-1 (E[kc], V[kc-1]) complete
        } else {
            cpa_wait<0>();   // everything (incl. V[31]) complete
        }
        __syncthreads();   // B: E[kc], V[kc-1], sPb[(kc-1)&1] visible

        if (w < 4) {
            if (kc < 32) {
                const float* cE = sEraw + (kc & 1) * (64 * 68);
                __nv_bfloat16* dP = sPb + (kc & 1) * (64 * 72);
                const size_t gk = (size_t)kc * 64;
#pragma unroll
                for (int i = 0; i < 8; i++) {
                    int idx = i * 32 + l;
                    int r = band + (idx >> 4);
                    int cc = (idx & 15) << 2;
                    float4 v = *(const float4*)&cE[r * 68 + cc];
                    float iv = sInv[r];
                    v.x *= iv; v.y *= iv; v.z *= iv; v.w *= iv;
                    *(float4*)&Eb[(size_t)r * NS + gk + cc] = v;
                    *(uint32_t*)&dP[r * 72 + cc]     = pack_bf2(v.x, v.y);
                    *(uint32_t*)&dP[r * 72 + cc + 2] = pack_bf2(v.z, v.w);
                }
            }
        } else if (kc >= 1) {
            const int kp = kc - 1;
            const __nv_bfloat16* cP = sPb + (kp & 1) * (64 * 72);
            const __nv_bfloat16* cV = sVh + (kp & 1) * (64 * 72);
#pragma unroll
            for (int kk = 0; kk < 4; kk++) {
                wmma::fragment<wmma::matrix_a, 16, 16, 16, __nv_bfloat16, wmma::row_major> af[2];
                wmma::fragment<wmma::matrix_b, 16, 16, 16, __nv_bfloat16, wmma::row_major> bf[2];
#pragma unroll
                for (int i = 0; i < 2; i++)
                    wmma::load_matrix_sync(af[i], &cP[(wm * 32 + i * 16) * 72 + kk * 16], 72);
#pragma unroll
                for (int j = 0; j < 2; j++)
                    wmma::load_matrix_sync(bf[j], &cV[(kk * 16) * 72 + wn * 32 + j * 16], 72);
#pragma unroll
                for (int i = 0; i < 2; i++)
#pragma unroll
                    for (int j = 0; j < 2; j++)
                        wmma::mma_sync(acc[i][j], af[i], bf[j], acc[i][j]);
            }
        }
    }

    __syncthreads();
    // epilogue: MMA warps stage f32 accs in sEraw (per-warp 32x36 region),
    // emit bf16 ctx. 4 warps * 4608B = 18432 <= 34816.
    if (w >= 4) {
        float* stg = sEraw + wv * (32 * 36);
#pragma unroll
        for (int i = 0; i < 2; i++)
#pragma unroll
            for (int j = 0; j < 2; j++)
                wmma::store_matrix_sync(&stg[(i * 16) * 36 + j * 16], acc[i][j], 36,
                                        wmma::mem_row_major);
        __syncwarp();
        const float* row = stg + l * 36;
        uint32_t pk[16];
#pragma unroll
        for (int j = 0; j < 16; j++) pk[j] = pack_bf2(row[2 * j], row[2 * j + 1]);
        __nv_bfloat16* gp = g_ctxh + (size_t)(b * NS + m0 + wm * 32 + l) * ND + h * NDH + wn * 32;
#pragma unroll
        for (int j = 0; j < 4; j++)
            *(uint4*)(gp + j * 8) = make_uint4(pk[4 * j], pk[4 * j + 1], pk[4 * j + 2], pk[4 * j + 3]);
    }
}

// ---------------------------------------------------------------------------
// Residual + LayerNorm
// ---------------------------------------------------------------------------
__global__ __launch_bounds__(256) void ln_kernel(const float* __restrict__ resid,
                                                 float* __restrict__ out) {
    const int row = blockIdx.x;
    const int tid = threadIdx.x;

    float4 f  = *(const float4*)&g_fc[(size_t)row * ND + tid * 4];
    float4 rr = *(const float4*)&resid[(size_t)row * ND + tid * 4];
    float4 y;
    y.x = f.x + rr.x; y.y = f.y + rr.y; y.z = f.z + rr.z; y.w = f.w + rr.w;

    float s = y.x + y.y + y.z + y.w;
    float q = y.x * y.x + y.y * y.y + y.z * y.z + y.w * y.w;
#pragma unroll
    for (int off = 16; off > 0; off >>= 1) {
        s += __shfl_down_sync(0xffffffffu, s, off);
        q += __shfl_down_sync(0xffffffffu, q, off);
    }
    __shared__ float ss[8], sq[8];
    __shared__ float mu_s, rs_s;
    if ((tid & 31) == 0) { ss[tid >> 5] = s; sq[tid >> 5] = q; }
    __syncthreads();
    if (tid == 0) {
        float S = 0.0f, Q = 0.0f;
#pragma unroll
        for (int i = 0; i < 8; i++) { S += ss[i]; Q += sq[i]; }
        float mu  = S * (1.0f / ND);
        float var = Q * (1.0f / ND) - mu * mu;
        mu_s = mu;
        rs_s = rsqrtf(var + LN_EPS);
    }
    __syncthreads();
    const float mu = mu_s, rs = rs_s;
    float4 o;
    o.x = (y.x - mu) * rs; o.y = (y.y - mu) * rs;
    o.z = (y.z - mu) * rs; o.w = (y.w - mu) * rs;
    *(float4*)&out[(size_t)row * ND + tid * 4] = o;
}

// ---------------------------------------------------------------------------
extern "C" void kernel_launch(void* const* d_in, const int* in_sizes, int n_in,
                              void* d_out, int out_size) {
    const float* inQ = (const float*)d_in[0];
    const float* inK = (const float*)d_in[1];
    const float* inV = (const float*)d_in[2];
    const unsigned char* mask = (const unsigned char*)d_in[3];
    const float* WQ  = (const float*)d_in[4];
    const float* WK  = (const float*)d_in[5];
    const float* WV  = (const float*)d_in[6];
    const float* Wfc = (const float*)d_in[7];

    float* out  = (float*)d_out;
    float* attn = out + OUT_ELEMS;

    void *pFc, *pInVh, *pWVh, *pWfch, *pVh, *pCtxh;
    cudaGetSymbolAddress(&pFc, g_fc);
    cudaGetSymbolAddress(&pInVh, g_inVh);
    cudaGetSymbolAddress(&pWVh, g_WVh);
    cudaGetSymbolAddress(&pWfch, g_Wfch);
    cudaGetSymbolAddress(&pVh, g_Vh);
    cudaGetSymbolAddress(&pCtxh, g_ctxh);

    cudaFuncSetAttribute(escore_kernel, cudaFuncAttributeMaxDynamicSharedMemorySize, ESC_SMEM);
    cudaFuncSetAttribute(ctxnorm_kernel, cudaFuncAttributeMaxDynamicSharedMemorySize, CTX_SMEM);

    // all 7 input conversions in one launch
    cvt_all<<<dim3((TOK * ND / 4 + 255) / 256, 7), 256>>>(inQ, WQ, inK, WK, inV, WV, Wfc);

    // Q, K projections in fp16 (same mantissa as tf32; direct fp16 output)
    qk_gemm_h<<<dim3(8, 32, 2), 256>>>(0.0f);

    // V projection in bf16, direct bf16 output
    gemm_bf16_obf<<<dim3(8, 32), 256>>>((const __nv_bfloat16*)pInVh, (const __nv_bfloat16*)pWVh,
                                        (__nv_bfloat16*)pVh);

    escore_kernel<<<dim3(32, 32), 256, ESC_SMEM>>>(mask, attn);

    ctxnorm_kernel<<<dim3(32, 32), 256, CTX_SMEM>>>(attn);

    gemm_bf16<<<dim3(8, 32), 256>>>((const __nv_bfloat16*)pCtxh, (const __nv_bfloat16*)pWfch,
                                    (float*)pFc);

    ln_kernel<<<TOK, 256>>>(inQ, out);
}

// round 16
// speedup vs baseline: 1.0468x; 1.0468x over previous
#include <cuda_runtime.h>
#include <cuda_bf16.h>
#include <cuda_fp16.h>
#include <mma.h>
#include <cstdint>
#include <cstddef>

using namespace nvcuda;

// Problem shape (fixed): B=2, S=2048, D=1024, H=16, Dh=64
#define NB 2
#define NS 2048
#define ND 1024
#define NH 16
#define NDH 64
#define TOK (NB*NS)
#define OUT_ELEMS (4194304)
#define SCALE 0.125f
#define LN_EPS 1e-5f

// ---- scratch (__device__ globals; no allocation allowed) ----
__device__ float g_fc[TOK*ND];                 // fc projection output (f32)
__device__ float g_inv[32 * NS];               // 1/rowsum per [bh][row]
__device__ __half g_Qh[TOK*ND];                // fp16 Q projection
__device__ __half g_Kh[TOK*ND];                // fp16 K projection
__device__ __half g_inQh[TOK*ND];              // fp16 input_Q
__device__ __half g_WQh[ND*ND];                // fp16 W_Q
__device__ __half g_inKh[TOK*ND];              // fp16 input_K
__device__ __half g_WKh[ND*ND];                // fp16 W_K
__device__ __nv_bfloat16 g_inVh[TOK*ND];       // bf16 input_V
__device__ __nv_bfloat16 g_WVh[ND*ND];         // bf16 W_V
__device__ __nv_bfloat16 g_Wfch[ND*ND];        // bf16 W_fc
__device__ __nv_bfloat16 g_Vh[TOK*ND];         // bf16 V projection
__device__ __nv_bfloat16 g_ctxh[TOK*ND];       // bf16 context

// ---------------------------------------------------------------------------
__device__ __forceinline__ void cpa16(void* s, const void* g) {
    uint32_t sa = (uint32_t)__cvta_generic_to_shared(s);
    asm volatile("cp.async.ca.shared.global [%0], [%1], 16;" :: "r"(sa), "l"(g));
}
__device__ __forceinline__ void cpa_commit() {
    asm volatile("cp.async.commit_group;" ::: "memory");
}
template <int N>
__device__ __forceinline__ void cpa_wait() {
    asm volatile("cp.async.wait_group %0;" :: "n"(N) : "memory");
}

__device__ __forceinline__ uint32_t pack_bf2(float a, float b) {
    __nv_bfloat162 t = __float22bfloat162_rn(make_float2(a, b));
    return *(uint32_t*)&t;
}
__device__ __forceinline__ uint32_t pack_hf2(float a, float b) {
    __half2 t = __float22half2_rn(make_float2(a, b));
    return *(uint32_t*)&t;
}

// ---------------------------------------------------------------------------
// One launch converting all 7 inputs: z=0..3 -> fp16 (QK path),
// z=4..6 -> bf16 (V/fc path).
// ---------------------------------------------------------------------------
__global__ __launch_bounds__(256) void cvt_all(const float* __restrict__ inQ,
                                               const float* __restrict__ WQ,
                                               const float* __restrict__ inK,
                                               const float* __restrict__ WK,
                                               const float* __restrict__ inV,
                                               const float* __restrict__ WV,
                                               const float* __restrict__ Wfc) {
    const int z = blockIdx.y;
    const int n = (z == 0 || z == 2 || z == 4) ? TOK * ND : ND * ND;
    int i = (blockIdx.x * 256 + threadIdx.x) * 4;
    if (i >= n) return;
    const float* s;
    switch (z) {
        case 0: s = inQ; break;
        case 1: s = WQ; break;
        case 2: s = inK; break;
        case 3: s = WK; break;
        case 4: s = inV; break;
        case 5: s = WV; break;
        default: s = Wfc; break;
    }
    float4 v = *(const float4*)&s[i];
    if (z < 4) {
        __half* d = (z == 0) ? g_inQh : (z == 1) ? g_WQh : (z == 2) ? g_inKh : g_WKh;
        *(uint32_t*)&d[i]     = pack_hf2(v.x, v.y);
        *(uint32_t*)&d[i + 2] = pack_hf2(v.z, v.w);
    } else {
        __nv_bfloat16* d = (z == 4) ? g_inVh : (z == 5) ? g_WVh : g_Wfch;
        *(uint32_t*)&d[i]     = pack_bf2(v.x, v.y);
        *(uint32_t*)&d[i + 2] = pack_bf2(v.z, v.w);
    }
}

// ---------------------------------------------------------------------------
// fp16 GEMM with direct fp16 output: C half = A half @ B half (f32 accum).
// BK=32, 2-stage cp.async, BM=BN=128, 8 warps, warp tile 64x32.
// ---------------------------------------------------------------------------
#define LOADHH(sA, sB, A, Bw, st, k0)                                                  \
    {                                                                                  \
        _Pragma("unroll")                                                              \
        for (int i = 0; i < 2; i++) {                                                  \
            int idx = tid + i * 256;                                                   \
            int ra = idx >> 2, ca = (idx & 3) << 3;                                    \
            cpa16(&sA[st][ra][ca], &A[(size_t)(m0 + ra) * ND + (k0) + ca]);            \
            int rb = idx >> 4, cb = (idx & 15) << 3;                                   \
            cpa16(&sB[st][rb][cb], &Bw[(size_t)((k0) + rb) * ND + n0 + cb]);           \
        }                                                                              \
        cpa_commit();                                                                  \
    }

__global__ __launch_bounds__(256, 2) void qk_gemm_h(float dummy) {
    __shared__ __half sA[2][128][40];
    __shared__ __half sB[2][32][136];

    const int tid = threadIdx.x;
    const int w   = tid >> 5;
    const int l   = tid & 31;
    const int wm  = w >> 2;
    const int wn  = w & 3;
    const int m0  = blockIdx.y * 128;
    const int n0  = blockIdx.x * 128;
    const int z   = blockIdx.z;

    const __half* A  = (z == 0) ? g_inQh : g_inKh;
    const __half* Bw = (z == 0) ? g_WQh  : g_WKh;
    __half*       C  = (z == 0) ? g_Qh   : g_Kh;

    wmma::fragment<wmma::accumulator, 16, 16, 16, float> acc[4][2];
#pragma unroll
    for (int i = 0; i < 4; i++)
#pragma unroll
        for (int j = 0; j < 2; j++) wmma::fill_fragment(acc[i][j], 0.0f);

    LOADHH(sA, sB, A, Bw, 0, 0);

    for (int kt = 0; kt < 32; kt++) {
        if (kt < 31) {
            LOADHH(sA, sB, A, Bw, (kt + 1) & 1, (kt + 1) * 32);
            cpa_wait<1>();
        } else {
            cpa_wait<0>();
        }
        __syncthreads();
        const int st = kt & 1;
#pragma unroll
        for (int ks = 0; ks < 32; ks += 16) {
            wmma::fragment<wmma::matrix_a, 16, 16, 16, __half, wmma::row_major> af[4];
            wmma::fragment<wmma::matrix_b, 16, 16, 16, __half, wmma::row_major> bf[2];
#pragma unroll
            for (int i = 0; i < 4; i++)
                wmma::load_matrix_sync(af[i], &sA[st][wm * 64 + i * 16][ks], 40);
#pragma unroll
            for (int j = 0; j < 2; j++)
                wmma::load_matrix_sync(bf[j], &sB[st][ks][wn * 32 + j * 16], 136);
#pragma unroll
            for (int i = 0; i < 4; i++)
#pragma unroll
                for (int j = 0; j < 2; j++)
                    wmma::mma_sync(acc[i][j], af[i], bf[j], acc[i][j]);
        }
        __syncthreads();
    }

    float* stg = (float*)sA + (size_t)w * (16 * 36);
#pragma unroll
    for (int i = 0; i < 4; i++) {
        wmma::store_matrix_sync(&stg[0],  acc[i][0], 36, wmma::mem_row_major);
        wmma::store_matrix_sync(&stg[16], acc[i][1], 36, wmma::mem_row_major);
        __syncwarp();
        const int r  = l & 15;
        const int hf = l >> 4;
        const float* row = stg + r * 36 + hf * 16;
        uint32_t pk[8];
#pragma unroll
        for (int q = 0; q < 8; q++) pk[q] = pack_hf2(row[2 * q], row[2 * q + 1]);
        __half* gp = C + (size_t)(m0 + wm * 64 + i * 16 + r) * ND + n0 + wn * 32 + hf * 16;
        *(uint4*)gp       = make_uint4(pk[0], pk[1], pk[2], pk[3]);
        *(uint4*)(gp + 8) = make_uint4(pk[4], pk[5], pk[6], pk[7]);
        __syncwarp();
    }
}

// ---------------------------------------------------------------------------
// bf16 GEMM: C f32 = A bf16 @ B bf16 (fc projection).
// ---------------------------------------------------------------------------
__global__ __launch_bounds__(256, 2) void gemm_bf16(const __nv_bfloat16* __restrict__ A,
                                                    const __nv_bfloat16* __restrict__ Bw,
                                                    float* __restrict__ C) {
    __shared__ __nv_bfloat16 sA[2][128][40];
    __shared__ __nv_bfloat16 sB[2][32][136];

    const int tid = threadIdx.x;
    const int w   = tid >> 5;
    const int wm  = w >> 2;
    const int wn  = w & 3;
    const int m0  = blockIdx.y * 128;
    const int n0  = blockIdx.x * 128;

    wmma::fragment<wmma::accumulator, 16, 16, 16, float> acc[4][2];
#pragma unroll
    for (int i = 0; i < 4; i++)
#pragma unroll
        for (int j = 0; j < 2; j++) wmma::fill_fragment(acc[i][j], 0.0f);

    LOADHH(sA, sB, A, Bw, 0, 0);

    for (int kt = 0; kt < 32; kt++) {
        if (kt < 31) {
            LOADHH(sA, sB, A, Bw, (kt + 1) & 1, (kt + 1) * 32);
            cpa_wait<1>();
        } else {
            cpa_wait<0>();
        }
        __syncthreads();
        const int st = kt & 1;
#pragma unroll
        for (int ks = 0; ks < 32; ks += 16) {
            wmma::fragment<wmma::matrix_a, 16, 16, 16, __nv_bfloat16, wmma::row_major> af[4];
            wmma::fragment<wmma::matrix_b, 16, 16, 16, __nv_bfloat16, wmma::row_major> bf[2];
#pragma unroll
            for (int i = 0; i < 4; i++)
                wmma::load_matrix_sync(af[i], &sA[st][wm * 64 + i * 16][ks], 40);
#pragma unroll
            for (int j = 0; j < 2; j++)
                wmma::load_matrix_sync(bf[j], &sB[st][ks][wn * 32 + j * 16], 136);
#pragma unroll
            for (int i = 0; i < 4; i++)
#pragma unroll
                for (int j = 0; j < 2; j++)
                    wmma::mma_sync(acc[i][j], af[i], bf[j], acc[i][j]);
        }
        __syncthreads();
    }

#pragma unroll
    for (int i = 0; i < 4; i++)
#pragma unroll
        for (int j = 0; j < 2; j++)
            wmma::store_matrix_sync(&C[(size_t)(m0 + wm * 64 + i * 16) * ND + n0 + wn * 32 + j * 16],
                                    acc[i][j], ND, wmma::mem_row_major);
}

// ---------------------------------------------------------------------------
// bf16 GEMM with DIRECT bf16 output (V projection).
// ---------------------------------------------------------------------------
__global__ __launch_bounds__(256, 2) void gemm_bf16_obf(const __nv_bfloat16* __restrict__ A,
                                                        const __nv_bfloat16* __restrict__ Bw,
                                                        __nv_bfloat16* __restrict__ C) {
    __shared__ __nv_bfloat16 sA[2][128][40];
    __shared__ __nv_bfloat16 sB[2][32][136];

    const int tid = threadIdx.x;
    const int w   = tid >> 5;
    const int l   = tid & 31;
    const int wm  = w >> 2;
    const int wn  = w & 3;
    const int m0  = blockIdx.y * 128;
    const int n0  = blockIdx.x * 128;

    wmma::fragment<wmma::accumulator, 16, 16, 16, float> acc[4][2];
#pragma unroll
    for (int i = 0; i < 4; i++)
#pragma unroll
        for (int j = 0; j < 2; j++) wmma::fill_fragment(acc[i][j], 0.0f);

    LOADHH(sA, sB, A, Bw, 0, 0);

    for (int kt = 0; kt < 32; kt++) {
        if (kt < 31) {
            LOADHH(sA, sB, A, Bw, (kt + 1) & 1, (kt + 1) * 32);
            cpa_wait<1>();
        } else {
            cpa_wait<0>();
        }
        __syncthreads();
        const int st = kt & 1;
#pragma unroll
        for (int ks = 0; ks < 32; ks += 16) {
            wmma::fragment<wmma::matrix_a, 16, 16, 16, __nv_bfloat16, wmma::row_major> af[4];
            wmma::fragment<wmma::matrix_b, 16, 16, 16, __nv_bfloat16, wmma::row_major> bf[2];
#pragma unroll
            for (int i = 0; i < 4; i++)
                wmma::load_matrix_sync(af[i], &sA[st][wm * 64 + i * 16][ks], 40);
#pragma unroll
            for (int j = 0; j < 2; j++)
                wmma::load_matrix_sync(bf[j], &sB[st][ks][wn * 32 + j * 16], 136);
#pragma unroll
            for (int i = 0; i < 4; i++)
#pragma unroll
                for (int j = 0; j < 2; j++)
                    wmma::mma_sync(acc[i][j], af[i], bf[j], acc[i][j]);
        }
        __syncthreads();
    }

    float* stg = (float*)sA + (size_t)w * (16 * 36);
#pragma unroll
    for (int i = 0; i < 4; i++) {
        wmma::store_matrix_sync(&stg[0],  acc[i][0], 36, wmma::mem_row_major);
        wmma::store_matrix_sync(&stg[16], acc[i][1], 36, wmma::mem_row_major);
        __syncwarp();
        const int r  = l & 15;
        const int hf = l >> 4;
        const float* row = stg + r * 36 + hf * 16;
        uint32_t pk[8];
#pragma unroll
        for (int q = 0; q < 8; q++) pk[q] = pack_bf2(row[2 * q], row[2 * q + 1]);
        __nv_bfloat16* gp = C + (size_t)(m0 + wm * 64 + i * 16 + r) * ND + n0 + wn * 32 + hf * 16;
        *(uint4*)gp       = make_uint4(pk[0], pk[1], pk[2], pk[3]);
        *(uint4*)(gp + 8) = make_uint4(pk[4], pk[5], pk[6], pk[7]);
        __syncwarp();
    }
}
#undef LOADHH

// ---------------------------------------------------------------------------
// escore v7.1 — fp16 Q/K, mask in smem, 3 blocks/SM (proven round-15 win).
// grid = (32, 32), 256 threads.
// ---------------------------------------------------------------------------
#define ESC_SMEM (17408 + 256 + 9216 + 18432 + 12288)   // 57600 B

__global__ __launch_bounds__(256, 3) void escore_kernel(const unsigned char* __restrict__ mask,
                                                        float* __restrict__ attnOut) {
    extern __shared__ float sm[];
    float* sS   = sm;                                   // 64 x 68 f32
    float* sSum = sS + 64 * 68;                         // 64
    __half* sQ  = (__half*)(sSum + 64);                 // 64 x 72 half
    __half* sK  = sQ + 64 * 72;                         // 2 x (64 x 72) half
    unsigned char* sMask = (unsigned char*)(sK + 2 * 64 * 72);  // 3 x 4096

    const int tid = threadIdx.x;
    const int w   = tid >> 5;
    const int l   = tid & 31;
    const int bh  = blockIdx.y;
    const int b   = bh >> 4;
    const int h   = bh & 15;
    const int q0  = blockIdx.x * 64;

    const __half* Qb = g_Qh + ((size_t)(b * NS + q0)) * ND + h * NDH;
    const __half* Kb = g_Kh + ((size_t)b * NS) * ND + h * NDH;
    const unsigned char* Mb = mask + ((size_t)(b * NS + q0)) * NS;

    const int mrw = tid >> 2;
    const int mcc = (tid & 3) << 4;

#pragma unroll
    for (int i = 0; i < 2; i++) {
        int idx = tid + i * 256;
        int r = idx >> 3, c = (idx & 7) << 3;
        cpa16(&sQ[r * 72 + c], &Qb[(size_t)r * ND + c]);
        cpa16(&sK[r * 72 + c], &Kb[(size_t)r * ND + c]);
    }
    cpa16(&sMask[mrw * 64 + mcc], &Mb[(size_t)mrw * NS + mcc]);
    cpa_commit();
    if (tid < 64) sSum[tid] = 0.0f;

    const int wm = w >> 2;
    const int wn = w & 3;

    wmma::fragment<wmma::matrix_a, 16, 16, 16, __half, wmma::row_major> af[2][4];

    int mbuf = 0;

    for (int ct = 0; ct < 32; ct++) {
        const int mnext = (mbuf + 1 == 3) ? 0 : mbuf + 1;
        if (ct < 31) {
            __half* dst = sK + ((ct + 1) & 1) * (64 * 72);
            const __half* src = Kb + (size_t)(ct + 1) * 64 * ND;
#pragma unroll
            for (int i = 0; i < 2; i++) {
                int idx = tid + i * 256;
                int r = idx >> 3, c = (idx & 7) << 3;
                cpa16(&dst[r * 72 + c], &src[(size_t)r * ND + c]);
            }
            cpa16(&sMask[mnext * 4096 + mrw * 64 + mcc],
                  &Mb[(size_t)mrw * NS + (size_t)(ct + 1) * 64 + mcc]);
            cpa_commit();
            cpa_wait<1>();
        } else {
            cpa_wait<0>();
        }
        __syncthreads();   // A: K[ct], M[ct] (and Q at ct=0) visible

        if (ct == 0) {
#pragma unroll
            for (int i = 0; i < 2; i++)
#pragma unroll
                for (int kk = 0; kk < 4; kk++)
                    wmma::load_matrix_sync(af[i][kk], &sQ[(wm * 32 + i * 16) * 72 + kk * 16], 72);
        }

        const __half* sKt = sK + (ct & 1) * (64 * 72);
        wmma::fragment<wmma::accumulator, 16, 16, 16, float> acc[2];
        wmma::fill_fragment(acc[0], 0.0f);
        wmma::fill_fragment(acc[1], 0.0f);

#pragma unroll
        for (int kk = 0; kk < 4; kk++) {
            wmma::fragment<wmma::matrix_b, 16, 16, 16, __half, wmma::col_major> bf;
            wmma::load_matrix_sync(bf, &sKt[(wn * 16) * 72 + kk * 16], 72);
            wmma::mma_sync(acc[0], af[0][kk], bf, acc[0]);
            wmma::mma_sync(acc[1], af[1][kk], bf, acc[1]);
        }
#pragma unroll
        for (int i = 0; i < 2; i++)
            wmma::store_matrix_sync(&sS[(wm * 32 + i * 16) * 68 + wn * 16], acc[i], 68,
                                    wmma::mem_row_major);
        __syncthreads();   // B: sS complete; K buffer reuse guarded

        const int c0 = ct * 64;
        const unsigned char* mTile = sMask + mbuf * 4096;
#pragma unroll
        for (int pass = 0; pass < 4; pass++) {
            const int r  = w * 8 + pass * 2 + (l >> 4);
            const int cc = (l & 15) << 2;
            float4 v = *(const float4*)&sS[r * 68 + cc];
            uchar4 mk = *(const uchar4*)&mTile[r * 64 + cc];
            v.x = mk.x ? 0.0f : __expf(v.x * SCALE);
            v.y = mk.y ? 0.0f : __expf(v.y * SCALE);
            v.z = mk.z ? 0.0f : __expf(v.z * SCALE);
            v.w = mk.w ? 0.0f : __expf(v.w * SCALE);
            float* erow = attnOut + ((size_t)(bh * NS + q0 + r)) * NS + c0;
            *(float4*)&erow[cc] = v;
            float s = v.x + v.y + v.z + v.w;
#pragma unroll
            for (int off = 8; off > 0; off >>= 1)
                s += __shfl_xor_sync(0xffffffffu, s, off);
            if ((l & 15) == 0) sSum[r] += s;
        }
        mbuf = mnext;
    }

    __syncthreads();
    if (tid < 64) g_inv[(size_t)bh * NS + q0 + tid] = 1.0f / sSum[tid];
}

// ---------------------------------------------------------------------------
// ctxnorm v3.1 — REVERTED to round-14 config (128-row tiles, 512 threads):
// v4's 64-row tiles doubled V traffic and regressed. Warp-specialized,
// lagged-V prefetch (race-free). grid = (16, 32), 512 threads.
// ---------------------------------------------------------------------------
#define CTX_ER   (2 * 128 * 68 * 4)     // 69632
#define CTX_VH   (2 * 64 * 72 * 2)      // 18432
#define CTX_PB   (2 * 128 * 72 * 2)     // 73728
#define CTX_SMEM (CTX_ER + CTX_VH + CTX_PB + 512)   // 162304

__global__ __launch_bounds__(512) void ctxnorm_kernel(float* __restrict__ attn) {
    extern __shared__ char smc[];
    float*         sEraw = (float*)smc;                               // 2 x 128 x 68
    __nv_bfloat16* sVh   = (__nv_bfloat16*)(smc + CTX_ER);            // 2 x 64 x 72
    __nv_bfloat16* sPb   = (__nv_bfloat16*)(smc + CTX_ER + CTX_VH);   // 2 x 128 x 72
    float*         sInv  = (float*)(smc + CTX_ER + CTX_VH + CTX_PB);  // 128

    const int tid = threadIdx.x;
    const int w   = tid >> 5;
    const int l   = tid & 31;
    const int bh  = blockIdx.y;
    const int b   = bh >> 4;
    const int h   = bh & 15;
    const int m0  = blockIdx.x * 128;

    float* Eb = attn + ((size_t)bh * NS + m0) * NS;
    const __nv_bfloat16* Vb = g_Vh + ((size_t)b * NS) * ND + h * NDH;

    if (tid < 128) sInv[tid] = g_inv[(size_t)bh * NS + m0 + tid];

    // pre-loop group: E chunk 0 only (V[0] comes with iteration 0's group)
#pragma unroll
    for (int i = 0; i < 4; i++) {
        int idx = tid + i * 512;
        int er = idx >> 4, ec = (idx & 15) << 2;
        cpa16(&sEraw[er * 68 + ec], &Eb[(size_t)er * NS + ec]);
    }
    cpa_commit();

    const int wv = w - 8;
    const int wm = wv >> 1, wn = wv & 1;    // MMA warps: 4(m) x 2(n), 32x32
    const int band = w * 16;                // epi warps (w<8): 16-row band

    wmma::fragment<wmma::accumulator, 16, 16, 16, float> acc[2][2];
    if (w >= 8) {
#pragma unroll
        for (int i = 0; i < 2; i++)
#pragma unroll
            for (int j = 0; j < 2; j++) wmma::fill_fragment(acc[i][j], 0.0f);
    }

    for (int kc = 0; kc <= 32; kc++) {
        __syncthreads();   // A: prior compute done -> buffer reuse safe
        if (kc < 32) {
            // group kc: E[kc+1] (if it exists) + V[kc]
            if (kc + 1 < 32) {
                float* dE = sEraw + ((kc + 1) & 1) * (128 * 68);
#pragma unroll
                for (int i = 0; i < 4; i++) {
                    int idx = tid + i * 512;
                    int er = idx >> 4, ec = (idx & 15) << 2;
                    cpa16(&dE[er * 68 + ec],
                          &Eb[(size_t)er * NS + (size_t)(kc + 1) * 64 + ec]);
                }
            }
            {
                __nv_bfloat16* dV = sVh + (kc & 1) * (64 * 72);
                int vr = tid >> 3, vc = (tid & 7) << 3;
                cpa16(&dV[vr * 72 + vc], &Vb[(size_t)(kc * 64 + vr) * ND + vc]);
            }
            cpa_commit();
            cpa_wait<1>();   // group kc-1 (E[kc], V[kc-1]) complete
        } else {
            cpa_wait<0>();   // everything (incl. V[31]) complete
        }
        __syncthreads();   // B: E[kc], V[kc-1], sPb[(kc-1)&1] visible

        if (w < 8) {
            if (kc < 32) {
                const float* cE = sEraw + (kc & 1) * (128 * 68);
                __nv_bfloat16* dP = sPb + (kc & 1) * (128 * 72);
                const size_t gk = (size_t)kc * 64;
#pragma unroll
                for (int i = 0; i < 8; i++) {
                    int idx = i * 32 + l;
                    int r = band + (idx >> 4);
                    int cc = (idx & 15) << 2;
                    float4 v = *(const float4*)&cE[r * 68 + cc];
                    float iv = sInv[r];
                    v.x *= iv; v.y *= iv; v.z *= iv; v.w *= iv;
                    *(float4*)&Eb[(size_t)r * NS + gk + cc] = v;
                    *(uint32_t*)&dP[r * 72 + cc]     = pack_bf2(v.x, v.y);
                    *(uint32_t*)&dP[r * 72 + cc + 2] = pack_bf2(v.z, v.w);
                }
            }
        } else if (kc >= 1) {
            const int kp = kc - 1;
            const __nv_bfloat16* cP = sPb + (kp & 1) * (128 * 72);
            const __nv_bfloat16* cV = sVh + (kp & 1) * (64 * 72);
#pragma unroll
            for (int kk = 0; kk < 4; kk++) {
                wmma::fragment<wmma::matrix_a, 16, 16, 16, __nv_bfloat16, wmma::row_major> af[2];
                wmma::fragment<wmma::matrix_b, 16, 16, 16, __nv_bfloat16, wmma::row_major> bf[2];
#pragma unroll
                for (int i = 0; i < 2; i++)
                    wmma::load_matrix_sync(af[i], &cP[(wm * 32 + i * 16) * 72 + kk * 16], 72);
#pragma unroll
                for (int j = 0; j < 2; j++)
                    wmma::load_matrix_sync(bf[j], &cV[(kk * 16) * 72 + wn * 32 + j * 16], 72);
#pragma unroll
                for (int i = 0; i < 2; i++)
#pragma unroll
                    for (int j = 0; j < 2; j++)
                        wmma::mma_sync(acc[i][j], af[i], bf[j], acc[i][j]);
            }
        }
    }

    __syncthreads();
    // epilogue: MMA warps stage f32 accs in sEraw (per-warp region), emit bf16
    if (w >= 8) {
        float* stg = sEraw + wv * (32 * 36);
#pragma unroll
        for (int i = 0; i < 2; i++)
#pragma unroll
            for (int j = 0; j < 2; j++)
                wmma::store_matrix_sync(&stg[(i * 16) * 36 + j * 16], acc[i][j], 36,
                                        wmma::mem_row_major);
        __syncwarp();
        const float* row = stg + l * 36;
        uint32_t pk[16];
#pragma unroll
        for (int j = 0; j < 16; j++) pk[j] = pack_bf2(row[2 * j], row[2 * j + 1]);
        __nv_bfloat16* gp = g_ctxh + (size_t)(b * NS + m0 + wm * 32 + l) * ND + h * NDH + wn * 32;
#pragma unroll
        for (int j = 0; j < 4; j++)
            *(uint4*)(gp + j * 8) = make_uint4(pk[4 * j], pk[4 * j + 1], pk[4 * j + 2], pk[4 * j + 3]);
    }
}

// ---------------------------------------------------------------------------
// Residual + LayerNorm
// ---------------------------------------------------------------------------
__global__ __launch_bounds__(256) void ln_kernel(const float* __restrict__ resid,
                                                 float* __restrict__ out) {
    const int row = blockIdx.x;
    const int tid = threadIdx.x;

    float4 f  = *(const float4*)&g_fc[(size_t)row * ND + tid * 4];
    float4 rr = *(const float4*)&resid[(size_t)row * ND + tid * 4];
    float4 y;
    y.x = f.x + rr.x; y.y = f.y + rr.y; y.z = f.z + rr.z; y.w = f.w + rr.w;

    float s = y.x + y.y + y.z + y.w;
    float q = y.x * y.x + y.y * y.y + y.z * y.z + y.w * y.w;
#pragma unroll
    for (int off = 16; off > 0; off >>= 1) {
        s += __shfl_down_sync(0xffffffffu, s, off);
        q += __shfl_down_sync(0xffffffffu, q, off);
    }
    __shared__ float ss[8], sq[8];
    __shared__ float mu_s, rs_s;
    if ((tid & 31) == 0) { ss[tid >> 5] = s; sq[tid >> 5] = q; }
    __syncthreads();
    if (tid == 0) {
        float S = 0.0f, Q = 0.0f;
#pragma unroll
        for (int i = 0; i < 8; i++) { S += ss[i]; Q += sq[i]; }
        float mu  = S * (1.0f / ND);
        float var = Q * (1.0f / ND) - mu * mu;
        mu_s = mu;
        rs_s = rsqrtf(var + LN_EPS);
    }
    __syncthreads();
    const float mu = mu_s, rs = rs_s;
    float4 o;
    o.x = (y.x - mu) * rs; o.y = (y.y - mu) * rs;
    o.z = (y.z - mu) * rs; o.w = (y.w - mu) * rs;
    *(float4*)&out[(size_t)row * ND + tid * 4] = o;
}

// ---------------------------------------------------------------------------
extern "C" void kernel_launch(void* const* d_in, const int* in_sizes, int n_in,
                              void* d_out, int out_size) {
    const float* inQ = (const float*)d_in[0];
    const float* inK = (const float*)d_in[1];
    const float* inV = (const float*)d_in[2];
    const unsigned char* mask = (const unsigned char*)d_in[3];
    const float* WQ  = (const float*)d_in[4];
    const float* WK  = (const float*)d_in[5];
    const float* WV  = (const float*)d_in[6];
    const float* Wfc = (const float*)d_in[7];

    float* out  = (float*)d_out;
    float* attn = out + OUT_ELEMS;

    void *pFc, *pInVh, *pWVh, *pWfch, *pVh, *pCtxh;
    cudaGetSymbolAddress(&pFc, g_fc);
    cudaGetSymbolAddress(&pInVh, g_inVh);
    cudaGetSymbolAddress(&pWVh, g_WVh);
    cudaGetSymbolAddress(&pWfch, g_Wfch);
    cudaGetSymbolAddress(&pVh, g_Vh);
    cudaGetSymbolAddress(&pCtxh, g_ctxh);

    cudaFuncSetAttribute(escore_kernel, cudaFuncAttributeMaxDynamicSharedMemorySize, ESC_SMEM);
    cudaFuncSetAttribute(ctxnorm_kernel, cudaFuncAttributeMaxDynamicSharedMemorySize, CTX_SMEM);

    // all 7 input conversions in one launch
    cvt_all<<<dim3((TOK * ND / 4 + 255) / 256, 7), 256>>>(inQ, WQ, inK, WK, inV, WV, Wfc);

    // Q, K projections in fp16 (same mantissa as tf32; direct fp16 output)
    qk_gemm_h<<<dim3(8, 32, 2), 256>>>(0.0f);

    // V projection in bf16, direct bf16 output
    gemm_bf16_obf<<<dim3(8, 32), 256>>>((const __nv_bfloat16*)pInVh, (const __nv_bfloat16*)pWVh,
                                        (__nv_bfloat16*)pVh);

    escore_kernel<<<dim3(32, 32), 256, ESC_SMEM>>>(mask, attn);

    ctxnorm_kernel<<<dim3(16, 32), 512, CTX_SMEM>>>(attn);

    gemm_bf16<<<dim3(8, 32), 256>>>((const __nv_bfloat16*)pCtxh, (const __nv_bfloat16*)pWfch,
                                    (float*)pFc);

    ln_kernel<<<TOK, 256>>>(inQ, out);
}